// round 13
// baseline (speedup 1.0000x reference)
#include <cuda_runtime.h>
#include <cuda_fp16.h>
#include <math.h>
#include <stdint.h>

// Problem constants
#define BB    4
#define TT    2048
#define DIM   512
#define NH    8
#define DH    64
#define MROWS (BB*TT)      // 8192
#define CHUNK 16
#define NCH   (TT/CHUNK)   // 128
#define WIN   256
#define TBLK  64
#define SCH   64

#define L2DECAY (-0.15200309344504997f)   // log2(0.9)
#define D8      (0.43046721f)             // 0.9^8
#define DINV    (1.1111111111111112f)     // 0.9^-1
#define DM8INV  (2.3230573202841774f)     // 0.9^-8

// Scratch (allocation-free rule: __device__ globals)
__device__ __half g_ah [MROWS*DIM];
__device__ __half g_bh [MROWS*DIM];
__device__ __half g_gh [MROWS*DIM];
__device__ __half g_hgh[MROWS*DIM];
__device__ __half g_qh [MROWS*DIM];
__device__ float  g_rout[MROWS*DIM];   // retention output (separate branch)
__device__ float  g_cA  [BB*NCH*DIM];
__device__ float  g_cB  [BB*NCH*DIM];
__device__ float  g_pref[BB*NCH*DIM];
__device__ __half g_Wth[4][DIM*DIM];   // transposed fp16 weights [n][k]

__device__ __forceinline__ uint32_t smem_u32(const void* p) {
    uint32_t a;
    asm("{ .reg .u64 t; cvta.to.shared.u64 t, %1; cvt.u32.u64 %0, t; }"
        : "=r"(a) : "l"(p));
    return a;
}

// ---------------------------------------------------------------------------
// Fused weight transpose + fp16 convert
// ---------------------------------------------------------------------------
__global__ __launch_bounds__(256) void transposeW4h(
    const float* __restrict__ W0, const float* __restrict__ W1,
    const float* __restrict__ W2, const float* __restrict__ W3,
    __half* __restrict__ Wt)
{
    __shared__ float t[32][33];
    const float* W = (blockIdx.z == 0) ? W0 : (blockIdx.z == 1) ? W1
                   : (blockIdx.z == 2) ? W2 : W3;
    __half* Wtz = Wt + (size_t)blockIdx.z * DIM * DIM;
    const int tx = threadIdx.x, ty = threadIdx.y;
    const int k0 = blockIdx.x * 32, n0 = blockIdx.y * 32;
#pragma unroll
    for (int j = 0; j < 32; j += 8)
        t[ty + j][tx] = W[(size_t)(k0 + ty + j) * DIM + n0 + tx];
    __syncthreads();
#pragma unroll
    for (int j = 0; j < 32; j += 8)
        Wtz[(size_t)(n0 + ty + j) * DIM + k0 + tx] = __float2half(t[tx][ty + j]);
}

// ---------------------------------------------------------------------------
// f32 -> fp16 bulk convert
// ---------------------------------------------------------------------------
__global__ __launch_bounds__(256) void f2h_bulk(
    const float* __restrict__ x, __half* __restrict__ y)
{
    const size_t i = ((size_t)blockIdx.x * 256 + threadIdx.x) * 8;
    float4 v0 = *(const float4*)&x[i];
    float4 v1 = *(const float4*)&x[i + 4];
    __half2 h[4];
    h[0] = __floats2half2_rn(v0.x, v0.y);
    h[1] = __floats2half2_rn(v0.z, v0.w);
    h[2] = __floats2half2_rn(v1.x, v1.y);
    h[3] = __floats2half2_rn(v1.z, v1.w);
    *(uint4*)&y[i] = *(uint4*)h;
}

// ---------------------------------------------------------------------------
// GEMM mainloop: 256 thr, 8 warps, warp tile 32x64, BK=32,
// 3-stage cp.async.cg pipeline + ldmatrix + m16n8k16.
// ---------------------------------------------------------------------------
#define HSR    40
#define HABUF  (128 * HSR)
#define STGB   (2 * HABUF * 2)          // 20480 bytes
#define NSTG   3
#define PIPE_SMEM (NSTG * STGB)         // 61440 bytes

__device__ __forceinline__ void cp16(uint32_t dst, const void* src) {
    asm volatile("cp.async.cg.shared.global [%0], [%1], 16;"
                 :: "r"(dst), "l"(src));
}
#define CP_COMMIT() asm volatile("cp.async.commit_group;")
#define CP_WAIT1()  asm volatile("cp.async.wait_group 1;")

__device__ __forceinline__ void ldsm_x4(uint32_t r[4], uint32_t addr) {
    asm volatile("ldmatrix.sync.aligned.m8n8.x4.shared.b16 {%0,%1,%2,%3}, [%4];"
                 : "=r"(r[0]), "=r"(r[1]), "=r"(r[2]), "=r"(r[3]) : "r"(addr));
}

__device__ __forceinline__ void mma_f16(
    float c[4], const uint32_t a[4], uint32_t b0, uint32_t b1)
{
    asm volatile(
        "mma.sync.aligned.m16n8k16.row.col.f32.f16.f16.f32 "
        "{%0,%1,%2,%3}, {%4,%5,%6,%7}, {%8,%9}, {%0,%1,%2,%3};"
        : "+f"(c[0]), "+f"(c[1]), "+f"(c[2]), "+f"(c[3])
        : "r"(a[0]), "r"(a[1]), "r"(a[2]), "r"(a[3]), "r"(b0), "r"(b1));
}

__device__ __forceinline__ void gemm_mainloop(
    const __half* __restrict__ X, const __half* __restrict__ Wt,
    int m0, int n0, __half* sm, float c[2][8][4])
{
    const int tid  = threadIdx.x;
    const int lane = tid & 31;
    const int wid  = tid >> 5;
    const int warpM = wid & 3;
    const int warpN = wid >> 2;
    const int lrow = lane & 15;
    const int lcol = (lane >> 4) * 8;

    const uint32_t smbase = smem_u32(sm);
    const int arow = tid >> 1;
    const int ab   = (tid & 1) * 32;
    const __half* srcA0 = X  + (size_t)(m0 + arow) * DIM + (tid & 1) * 16;
    const __half* srcB0 = Wt + (size_t)(n0 + arow) * DIM + (tid & 1) * 16;
    const uint32_t dstA0 = smbase + arow * (HSR * 2) + ab;

    const uint32_t aoff0 = ((warpM * 32 +      lrow) * HSR + lcol) * 2;
    const uint32_t aoff1 = ((warpM * 32 + 16 + lrow) * HSR + lcol) * 2;
    uint32_t boff[4];
#pragma unroll
    for (int ng = 0; ng < 4; ng++)
        boff[ng] = 2 * HABUF + ((warpN * 64 + ng * 16 + lrow) * HSR + lcol) * 2;

#define ISSUE(stage, ch) do {                                   \
        uint32_t dA = dstA0 + (stage) * STGB;                   \
        const __half* sA = srcA0 + (ch) * 32;                   \
        cp16(dA, sA); cp16(dA + 16, sA + 8);                    \
        uint32_t dB = dA + HABUF * 2;                           \
        const __half* sB = srcB0 + (ch) * 32;                   \
        cp16(dB, sB); cp16(dB + 16, sB + 8);                    \
    } while (0)

    ISSUE(0, 0); CP_COMMIT();
    ISSUE(1, 1); CP_COMMIT();

    const int NCHK = DIM / 32;   // 16
    for (int ch = 0; ch < NCHK; ch++) {
        CP_WAIT1();
        __syncthreads();
        if (ch + 2 < NCHK) ISSUE((ch + 2) % NSTG, ch + 2);
        CP_COMMIT();

        const uint32_t stg = smbase + (ch % NSTG) * STGB;
#pragma unroll
        for (int ks = 0; ks < 2; ks++) {
            const uint32_t kso = ks * 32;
            uint32_t af[2][4];
            ldsm_x4(af[0], stg + aoff0 + kso);
            ldsm_x4(af[1], stg + aoff1 + kso);
#pragma unroll
            for (int ng = 0; ng < 4; ng++) {
                uint32_t bq[4];
                ldsm_x4(bq, stg + boff[ng] + kso);
#pragma unroll
                for (int mt = 0; mt < 2; mt++) {
                    mma_f16(c[mt][ng * 2],     af[mt], bq[0], bq[2]);
                    mma_f16(c[mt][ng * 2 + 1], af[mt], bq[1], bq[3]);
                }
            }
        }
    }
#undef ISSUE
}

// ---------------------------------------------------------------------------
// Fused a/b/g projections (z picks weight/bias/output/act), fp16 out
// ---------------------------------------------------------------------------
__global__ __launch_bounds__(256) void gemm3_h(
    const __half* __restrict__ X, const __half* __restrict__ Wth,
    const float* __restrict__ ba, const float* __restrict__ bbi,
    const float* __restrict__ bg,
    __half* __restrict__ Ca, __half* __restrict__ Cb, __half* __restrict__ Cg)
{
    extern __shared__ __half sm[];
    const int z = blockIdx.z;
    const __half* Wt = Wth + (size_t)z * DIM * DIM;
    const float* bias = (z == 0) ? ba : (z == 1) ? bbi : bg;
    __half* C = (z == 0) ? Ca : (z == 1) ? Cb : Cg;
    const int act = (z == 1) ? 0 : 1;
    const int m0 = blockIdx.y * 128;
    const int n0 = blockIdx.x * 128;

    float c[2][8][4];
#pragma unroll
    for (int mt = 0; mt < 2; mt++)
#pragma unroll
        for (int nt = 0; nt < 8; nt++)
#pragma unroll
            for (int r = 0; r < 4; r++) c[mt][nt][r] = 0.0f;

    gemm_mainloop(X, Wt, m0, n0, sm, c);

    const int lane = threadIdx.x & 31;
    const int wid  = threadIdx.x >> 5;
    const int g    = lane >> 2;
    const int t4   = lane & 3;
    const int warpM = wid & 3;
    const int warpN = wid >> 2;
#pragma unroll
    for (int mt = 0; mt < 2; mt++) {
#pragma unroll
        for (int nt = 0; nt < 8; nt++) {
            const int row  = m0 + warpM * 32 + mt * 16 + g;
            const int coln = n0 + warpN * 64 + nt * 8 + t4 * 2;
            const float b0 = bias[coln], b1 = bias[coln + 1];
            float v0 = c[mt][nt][0] + b0;
            float v1 = c[mt][nt][1] + b1;
            float v2 = c[mt][nt][2] + b0;
            float v3 = c[mt][nt][3] + b1;
            if (act) {
                v0 = 1.0f / (1.0f + __expf(-v0));
                v1 = 1.0f / (1.0f + __expf(-v1));
                v2 = 1.0f / (1.0f + __expf(-v2));
                v3 = 1.0f / (1.0f + __expf(-v3));
            }
            *(__half2*)&C[(size_t)row * DIM + coln]       = __floats2half2_rn(v0, v1);
            *(__half2*)&C[(size_t)(row + 8) * DIM + coln] = __floats2half2_rn(v2, v3);
        }
    }
}

// ---------------------------------------------------------------------------
// Final projection + merge: out = hg @ Wo^T + bo + g_rout
// ---------------------------------------------------------------------------
__global__ __launch_bounds__(256) void gemm1_f(
    const __half* __restrict__ X, const __half* __restrict__ Wt,
    const float* __restrict__ bias, const float* __restrict__ R,
    float* __restrict__ C)
{
    extern __shared__ __half sm[];
    const int m0 = blockIdx.y * 128;
    const int n0 = blockIdx.x * 128;

    float c[2][8][4];
#pragma unroll
    for (int mt = 0; mt < 2; mt++)
#pragma unroll
        for (int nt = 0; nt < 8; nt++)
#pragma unroll
            for (int r = 0; r < 4; r++) c[mt][nt][r] = 0.0f;

    gemm_mainloop(X, Wt, m0, n0, sm, c);

    const int lane = threadIdx.x & 31;
    const int wid  = threadIdx.x >> 5;
    const int g    = lane >> 2;
    const int t4   = lane & 3;
    const int warpM = wid & 3;
    const int warpN = wid >> 2;
#pragma unroll
    for (int mt = 0; mt < 2; mt++) {
#pragma unroll
        for (int nt = 0; nt < 8; nt++) {
            const int row  = m0 + warpM * 32 + mt * 16 + g;
            const int coln = n0 + warpN * 64 + nt * 8 + t4 * 2;
            const float b0 = bias[coln], b1 = bias[coln + 1];
            float2 r0 = *(const float2*)&R[(size_t)row * DIM + coln];
            float2 r1 = *(const float2*)&R[(size_t)(row + 8) * DIM + coln];
            *(float2*)&C[(size_t)row * DIM + coln] =
                make_float2(c[mt][nt][0] + b0 + r0.x, c[mt][nt][1] + b1 + r0.y);
            *(float2*)&C[(size_t)(row + 8) * DIM + coln] =
                make_float2(c[mt][nt][2] + b0 + r1.x, c[mt][nt][3] + b1 + r1.y);
        }
    }
}

// ---------------------------------------------------------------------------
// Chunked linear scan (CHUNK=16 -> 512 blocks per phase)
// ---------------------------------------------------------------------------
__global__ __launch_bounds__(256) void scan_chunks_h()
{
    const int d2 = threadIdx.x;
    const int c  = blockIdx.x;
    const int bb = blockIdx.y;
    const __half2* pa = (const __half2*)g_ah;
    const __half2* pb = (const __half2*)g_bh;
    size_t base = ((size_t)(bb * TT + c * CHUNK) * DIM) / 2 + d2;
    float A0 = 1.0f, A1 = 1.0f, h0 = 0.0f, h1 = 0.0f;
#pragma unroll
    for (int t = 0; t < CHUNK; t++) {
        float2 af = __half22float2(pa[base + (size_t)t * 256]);
        float2 bf = __half22float2(pb[base + (size_t)t * 256]);
        h0 = fmaf(af.x, h0, bf.x);
        h1 = fmaf(af.y, h1, bf.y);
        A0 *= af.x; A1 *= af.y;
    }
    const int idx = (bb * NCH + c) * DIM + 2 * d2;
    g_cA[idx] = A0; g_cA[idx + 1] = A1;
    g_cB[idx] = h0; g_cB[idx + 1] = h1;
}

__global__ __launch_bounds__(512) void scan_carry()
{
    const int d  = threadIdx.x;
    const int bb = blockIdx.x;
    float h = 0.0f;
#pragma unroll 8
    for (int c = 0; c < NCH; c++) {
        const int idx = (bb * NCH + c) * DIM + d;
        g_pref[idx] = h;
        h = fmaf(g_cA[idx], h, g_cB[idx]);
    }
}

__global__ __launch_bounds__(256) void scan_apply_h()
{
    const int d2 = threadIdx.x;
    const int c  = blockIdx.x;
    const int bb = blockIdx.y;
    const __half2* pa = (const __half2*)g_ah;
    const __half2* pb = (const __half2*)g_bh;
    const __half2* pg = (const __half2*)g_gh;
    __half2* phg = (__half2*)g_hgh;
    size_t base = ((size_t)(bb * TT + c * CHUNK) * DIM) / 2 + d2;
    float2 pf = *(float2*)&g_pref[(bb * NCH + c) * DIM + 2 * d2];
    float h0 = pf.x, h1 = pf.y;
#pragma unroll
    for (int t = 0; t < CHUNK; t++) {
        float2 af = __half22float2(pa[base + (size_t)t * 256]);
        float2 bf = __half22float2(pb[base + (size_t)t * 256]);
        float2 gf = __half22float2(pg[base + (size_t)t * 256]);
        h0 = fmaf(af.x, h0, bf.x);
        h1 = fmaf(af.y, h1, bf.y);
        phg[base + (size_t)t * 256] = __floats2half2_rn(h0 * gf.x, h1 * gf.y);
    }
}

// ---------------------------------------------------------------------------
// Retention via fp16 mma.sync + ldmatrix fragments (windowed, WIN=256)
// Tiles padded to 72 halves (144B) per row: 16B-aligned, conflict-free ldsm.
// ---------------------------------------------------------------------------
#define SRU  36   // u32 per tile row (72 halves, 144 bytes)

__device__ __forceinline__ uint32_t packh2(float lo, float hi) {
    __half2 h = __floats2half2_rn(lo, hi);
    return *(uint32_t*)&h;
}

__global__ __launch_bounds__(256) void retention_mma(
    const float* __restrict__ q, const float* __restrict__ k,
    const float* __restrict__ v, float* __restrict__ out)
{
    __shared__ __align__(16) uint32_t Qs[64 * SRU];
    __shared__ __align__(16) uint32_t Ks[64 * SRU];
    __shared__ __align__(16) uint32_t Ss[64 * SRU];
    __shared__ __align__(16) uint32_t Vt[64 * SRU];

    const int tid  = threadIdx.x;
    const int lane = tid & 31;
    const int wid  = tid >> 5;
    const int g    = lane >> 2;
    const int t4   = lane & 3;
    const int tb   = (wid & 3) * 16;      // warp t-strip
    const int nb   = (wid >> 2) * 32;     // warp n-strip (s for S, d for O)
    const int lrow  = lane & 15;
    const int lcolb = (lane >> 4) * 16;   // byte offset within a 32B k-step

    const int t0 = blockIdx.x * TBLK;
    const int hh = blockIdx.y;
    const int bb = blockIdx.z;

    const float* qb = q + (size_t)bb * TT * DIM + hh * DH;
    const float* kb = k + (size_t)bb * TT * DIM + hh * DH;
    const float* vb = v + (size_t)bb * TT * DIM + hh * DH;

    // staging maps
    const int row = tid >> 2;           // Q/K: t or s row 0..63
    const int dg  = (tid & 3) * 16;     // 16 floats along d
    const int vs0 = (tid & 15) * 4;     // V: s block (transposed map ->
    const int vd0 = (tid >> 4) * 4;     //    conflict-free Vt stores)

    // ---- load Q tile as fp16 ----
    {
        const float4* qrow = (const float4*)&qb[(size_t)(t0 + row) * DIM + dg];
        uint32_t tmp[8];
#pragma unroll
        for (int i = 0; i < 4; i++) {
            float4 x = qrow[i];
            tmp[2*i]   = packh2(x.x, x.y);
            tmp[2*i+1] = packh2(x.z, x.w);
        }
        *(uint4*)&Qs[row * SRU + (tid & 3) * 8]     = make_uint4(tmp[0], tmp[1], tmp[2], tmp[3]);
        *(uint4*)&Qs[row * SRU + (tid & 3) * 8 + 4] = make_uint4(tmp[4], tmp[5], tmp[6], tmp[7]);
    }
    __syncthreads();

    // ---- Q A-fragments via ldmatrix (cached across chunks) ----
    const uint32_t qbase = smem_u32(Qs);
    const uint32_t kbase = smem_u32(Ks);
    const uint32_t sbase = smem_u32(Ss);
    const uint32_t vbase = smem_u32(Vt);
    uint32_t afq[4][4];
#pragma unroll
    for (int kk = 0; kk < 4; kk++)
        ldsm_x4(afq[kk], qbase + (tb + lrow) * 144 + kk * 32 + lcolb);

    float dsv[4][2];
    dsv[0][0] = exp2f(-L2DECAY * (float)(nb + 2 * t4));
    dsv[0][1] = dsv[0][0] * DINV;
#pragma unroll
    for (int nf = 1; nf < 4; nf++) {
        dsv[nf][0] = dsv[nf-1][0] * DM8INV;
        dsv[nf][1] = dsv[nf-1][1] * DM8INV;
    }

    float co[4][4];
#pragma unroll
    for (int nf = 0; nf < 4; nf++)
#pragma unroll
        for (int r = 0; r < 4; r++) co[nf][r] = 0.0f;

    const int sBeg = (t0 >= WIN) ? (t0 - WIN) : 0;

    for (int s0 = sBeg; s0 <= t0; s0 += SCH) {
        // prefetch K, V chunk to registers
        float4 kx[4], vx[4];
        {
            const float4* krow = (const float4*)&kb[(size_t)(s0 + row) * DIM + dg];
#pragma unroll
            for (int i = 0; i < 4; i++) kx[i] = krow[i];
#pragma unroll
            for (int i = 0; i < 4; i++)
                vx[i] = *(const float4*)&vb[(size_t)(s0 + vs0 + i) * DIM + vd0];
        }
        __syncthreads();   // prior O-mma done reading Ks/Vt/Ss

        // stage K (row = s, cols = d halves)
        {
            uint32_t tmp[8];
#pragma unroll
            for (int i = 0; i < 4; i++) {
                tmp[2*i]   = packh2(kx[i].x, kx[i].y);
                tmp[2*i+1] = packh2(kx[i].z, kx[i].w);
            }
            *(uint4*)&Ks[row * SRU + (tid & 3) * 8]     = make_uint4(tmp[0], tmp[1], tmp[2], tmp[3]);
            *(uint4*)&Ks[row * SRU + (tid & 3) * 8 + 4] = make_uint4(tmp[4], tmp[5], tmp[6], tmp[7]);
        }
        // stage V transposed: Vt[d][s]; vx[i] holds row (s0+vs0+i), cols vd0..vd0+3
        {
            const float vr[4][4] = {
                {vx[0].x, vx[0].y, vx[0].z, vx[0].w},
                {vx[1].x, vx[1].y, vx[1].z, vx[1].w},
                {vx[2].x, vx[2].y, vx[2].z, vx[2].w},
                {vx[3].x, vx[3].y, vx[3].z, vx[3].w}};
#pragma unroll
            for (int j = 0; j < 4; j++) {
                Vt[(vd0 + j) * SRU + (vs0 >> 1)]     = packh2(vr[0][j], vr[1][j]);
                Vt[(vd0 + j) * SRU + (vs0 >> 1) + 1] = packh2(vr[2][j], vr[3][j]);
            }
        }
        __syncthreads();

        // ---- S = Q . K^T via ldmatrix fragments ----
        float cs[4][4];
#pragma unroll
        for (int nf = 0; nf < 4; nf++)
#pragma unroll
            for (int r = 0; r < 4; r++) cs[nf][r] = 0.0f;
#pragma unroll
        for (int kk = 0; kk < 4; kk++) {
#pragma unroll
            for (int ng = 0; ng < 2; ng++) {
                uint32_t bq[4];
                ldsm_x4(bq, kbase + (nb + ng * 16 + lrow) * 144 + kk * 32 + lcolb);
                mma_f16(cs[ng * 2],     afq[kk], bq[0], bq[2]);
                mma_f16(cs[ng * 2 + 1], afq[kk], bq[1], bq[3]);
            }
        }

        // ---- decay + mask, store S as fp16 ----
        const int off = t0 - s0;
        const float Dt0 = exp2f((float)(tb + g + off) * L2DECAY);
        const float Dt1 = Dt0 * D8;
#pragma unroll
        for (int nf = 0; nf < 4; nf++) {
            const int scol = nb + nf * 8 + 2 * t4;
            const int d0 = tb + g + off - scol;
            float w00 = (d0     >= 0) ? Dt0 * dsv[nf][0] : 0.0f;
            float w01 = (d0 - 1 >= 0) ? Dt0 * dsv[nf][1] : 0.0f;
            float w10 = (d0 + 8 >= 0) ? Dt1 * dsv[nf][0] : 0.0f;
            float w11 = (d0 + 7 >= 0) ? Dt1 * dsv[nf][1] : 0.0f;
            Ss[(tb + g)     * SRU + (nb >> 1) + nf * 4 + t4] = packh2(cs[nf][0] * w00, cs[nf][1] * w01);
            Ss[(tb + g + 8) * SRU + (nb >> 1) + nf * 4 + t4] = packh2(cs[nf][2] * w10, cs[nf][3] * w11);
        }
        __syncthreads();

        // ---- O += S . V via ldmatrix fragments ----
#pragma unroll
        for (int kk = 0; kk < 4; kk++) {
            uint32_t as[4];
            ldsm_x4(as, sbase + (tb + lrow) * 144 + kk * 32 + lcolb);
#pragma unroll
            for (int ng = 0; ng < 2; ng++) {
                uint32_t bq[4];
                ldsm_x4(bq, vbase + (nb + ng * 16 + lrow) * 144 + kk * 32 + lcolb);
                mma_f16(co[ng * 2],     as, bq[0], bq[2]);
                mma_f16(co[ng * 2 + 1], as, bq[1], bq[3]);
            }
        }
    }

    // pure store into g_rout (merged later by gemm1_f)
#pragma unroll
    for (int nf = 0; nf < 4; nf++) {
        const int col = hh * DH + nb + nf * 8 + 2 * t4;
        *(float2*)&out[((size_t)bb * TT + t0 + tb + g)     * DIM + col] =
            make_float2(co[nf][0], co[nf][1]);
        *(float2*)&out[((size_t)bb * TT + t0 + tb + g + 8) * DIM + col] =
            make_float2(co[nf][2], co[nf][3]);
    }
}

// ---------------------------------------------------------------------------
extern "C" void kernel_launch(void* const* d_in, const int* in_sizes, int n_in,
                              void* d_out, int out_size)
{
    const float* q  = (const float*)d_in[0];
    const float* k  = (const float*)d_in[1];
    const float* v  = (const float*)d_in[2];
    const float* Wa = (const float*)d_in[3];
    const float* ba = (const float*)d_in[4];
    const float* Wb = (const float*)d_in[5];
    const float* bb = (const float*)d_in[6];
    const float* Wg = (const float*)d_in[7];
    const float* bg = (const float*)d_in[8];
    const float* Wo = (const float*)d_in[9];
    const float* bo = (const float*)d_in[10];
    float* out = (float*)d_out;

    __half *pah, *pbh, *pgh, *phgh, *pqh, *pwth;
    float *prout;
    cudaGetSymbolAddress((void**)&pah,  g_ah);
    cudaGetSymbolAddress((void**)&pbh,  g_bh);
    cudaGetSymbolAddress((void**)&pgh,  g_gh);
    cudaGetSymbolAddress((void**)&phgh, g_hgh);
    cudaGetSymbolAddress((void**)&pqh,  g_qh);
    cudaGetSymbolAddress((void**)&pwth, g_Wth);
    cudaGetSymbolAddress((void**)&prout, g_rout);

    cudaFuncSetAttribute(gemm3_h, cudaFuncAttributeMaxDynamicSharedMemorySize, PIPE_SMEM);
    cudaFuncSetAttribute(gemm1_f, cudaFuncAttributeMaxDynamicSharedMemorySize, PIPE_SMEM);

    cudaStream_t s2;
    cudaStreamCreateWithFlags(&s2, cudaStreamNonBlocking);
    cudaEvent_t eFork, eW, eG3, eJoin;
    cudaEventCreateWithFlags(&eFork, cudaEventDisableTiming);
    cudaEventCreateWithFlags(&eW,    cudaEventDisableTiming);
    cudaEventCreateWithFlags(&eG3,   cudaEventDisableTiming);
    cudaEventCreateWithFlags(&eJoin, cudaEventDisableTiming);

    // Side stream: weight transpose (W-only) overlaps q->fp16 on main.
    cudaEventRecord(eFork, 0);
    cudaStreamWaitEvent(s2, eFork, 0);
    transposeW4h<<<dim3(DIM / 32, DIM / 32, 4), dim3(32, 8), 0, s2>>>(
        Wa, Wb, Wg, Wo, pwth);
    cudaEventRecord(eW, s2);

    // Main: q -> fp16, then the three projections (needs eW).
    f2h_bulk<<<(MROWS * DIM) / (256 * 8), 256>>>(q, pqh);
    cudaStreamWaitEvent(0, eW, 0);
    gemm3_h<<<dim3(DIM / 128, MROWS / 128, 3), 256, PIPE_SMEM>>>(
        pqh, pwth, ba, bb, bg, pah, pbh, pgh);
    cudaEventRecord(eG3, 0);

    // Side stream: retention starts after gemm3 (overlaps DRAM-bound scans).
    cudaStreamWaitEvent(s2, eG3, 0);
    retention_mma<<<dim3(TT / TBLK, NH, BB), 256, 0, s2>>>(q, k, v, prout);
    cudaEventRecord(eJoin, s2);

    // Main: scans (DRAM-bound, co-run with retention).
    scan_chunks_h<<<dim3(NCH, BB), 256>>>();
    scan_carry<<<BB, 512>>>();
    scan_apply_h<<<dim3(NCH, BB), 256>>>();

    // Join retention, then merging final projection.
    cudaStreamWaitEvent(0, eJoin, 0);
    gemm1_f<<<dim3(DIM / 128, MROWS / 128, 1), 256, PIPE_SMEM>>>(
        phgh, pwth + 3 * DIM * DIM, bo, prout, out);
}

// round 14
// speedup vs baseline: 1.1444x; 1.1444x over previous
#include <cuda_runtime.h>
#include <cuda_fp16.h>
#include <math.h>
#include <stdint.h>

// Problem constants
#define BB    4
#define TT    2048
#define DIM   512
#define NH    8
#define DH    64
#define MROWS (BB*TT)      // 8192
#define CHUNK 16
#define NCH   (TT/CHUNK)   // 128
#define WIN   256
#define TBLK  64
#define SCH   64

#define L2DECAY (-0.15200309344504997f)   // log2(0.9)
#define D8      (0.43046721f)             // 0.9^8
#define DINV    (1.1111111111111112f)     // 0.9^-1
#define DM8INV  (2.3230573202841774f)     // 0.9^-8

// Scratch (allocation-free rule: __device__ globals)
__device__ __half g_ah [MROWS*DIM];
__device__ __half g_bh [MROWS*DIM];
__device__ __half g_gh [MROWS*DIM];
__device__ __half g_hgh[MROWS*DIM];
__device__ __half g_qh [MROWS*DIM];
__device__ __half g_kh [MROWS*DIM];
__device__ __half g_vh [MROWS*DIM];
__device__ float  g_rout[MROWS*DIM];
__device__ float  g_cA  [BB*NCH*DIM];
__device__ float  g_cB  [BB*NCH*DIM];
__device__ float  g_pref[BB*NCH*DIM];
__device__ __half g_Wth[4][DIM*DIM];

__device__ __forceinline__ uint32_t smem_u32(const void* p) {
    uint32_t a;
    asm("{ .reg .u64 t; cvta.to.shared.u64 t, %1; cvt.u32.u64 %0, t; }"
        : "=r"(a) : "l"(p));
    return a;
}

// ---------------------------------------------------------------------------
// Fused weight transpose + fp16 convert
// ---------------------------------------------------------------------------
__global__ __launch_bounds__(256) void transposeW4h(
    const float* __restrict__ W0, const float* __restrict__ W1,
    const float* __restrict__ W2, const float* __restrict__ W3,
    __half* __restrict__ Wt)
{
    __shared__ float t[32][33];
    const float* W = (blockIdx.z == 0) ? W0 : (blockIdx.z == 1) ? W1
                   : (blockIdx.z == 2) ? W2 : W3;
    __half* Wtz = Wt + (size_t)blockIdx.z * DIM * DIM;
    const int tx = threadIdx.x, ty = threadIdx.y;
    const int k0 = blockIdx.x * 32, n0 = blockIdx.y * 32;
#pragma unroll
    for (int j = 0; j < 32; j += 8)
        t[ty + j][tx] = W[(size_t)(k0 + ty + j) * DIM + n0 + tx];
    __syncthreads();
#pragma unroll
    for (int j = 0; j < 32; j += 8)
        Wtz[(size_t)(n0 + ty + j) * DIM + k0 + tx] = __float2half(t[tx][ty + j]);
}

// ---------------------------------------------------------------------------
// f32 -> fp16 bulk convert
// ---------------------------------------------------------------------------
__global__ __launch_bounds__(256) void f2h_bulk(
    const float* __restrict__ x, __half* __restrict__ y)
{
    const size_t i = ((size_t)blockIdx.x * 256 + threadIdx.x) * 8;
    float4 v0 = *(const float4*)&x[i];
    float4 v1 = *(const float4*)&x[i + 4];
    __half2 h[4];
    h[0] = __floats2half2_rn(v0.x, v0.y);
    h[1] = __floats2half2_rn(v0.z, v0.w);
    h[2] = __floats2half2_rn(v1.x, v1.y);
    h[3] = __floats2half2_rn(v1.z, v1.w);
    *(uint4*)&y[i] = *(uint4*)h;
}

// ---------------------------------------------------------------------------
// cp.async / ldmatrix / mma primitives
// ---------------------------------------------------------------------------
__device__ __forceinline__ void cp16(uint32_t dst, const void* src) {
    asm volatile("cp.async.cg.shared.global [%0], [%1], 16;"
                 :: "r"(dst), "l"(src));
}
#define CP_COMMIT() asm volatile("cp.async.commit_group;")
#define CP_WAIT1()  asm volatile("cp.async.wait_group 1;")
#define CP_WAIT0()  asm volatile("cp.async.wait_group 0;")

__device__ __forceinline__ void ldsm_x4(uint32_t r[4], uint32_t addr) {
    asm volatile("ldmatrix.sync.aligned.m8n8.x4.shared.b16 {%0,%1,%2,%3}, [%4];"
                 : "=r"(r[0]), "=r"(r[1]), "=r"(r[2]), "=r"(r[3]) : "r"(addr));
}
__device__ __forceinline__ void ldsm_x4_t(uint32_t r[4], uint32_t addr) {
    asm volatile("ldmatrix.sync.aligned.m8n8.x4.trans.shared.b16 {%0,%1,%2,%3}, [%4];"
                 : "=r"(r[0]), "=r"(r[1]), "=r"(r[2]), "=r"(r[3]) : "r"(addr));
}

__device__ __forceinline__ void mma_f16(
    float c[4], const uint32_t a[4], uint32_t b0, uint32_t b1)
{
    asm volatile(
        "mma.sync.aligned.m16n8k16.row.col.f32.f16.f16.f32 "
        "{%0,%1,%2,%3}, {%4,%5,%6,%7}, {%8,%9}, {%0,%1,%2,%3};"
        : "+f"(c[0]), "+f"(c[1]), "+f"(c[2]), "+f"(c[3])
        : "r"(a[0]), "r"(a[1]), "r"(a[2]), "r"(a[3]), "r"(b0), "r"(b1));
}

// ---------------------------------------------------------------------------
// GEMM mainloop (R6/R12-proven): 256 thr, 8 warps, 32x64 warp tile, BK=32,
// 3-stage cp.async pipeline + ldmatrix + m16n8k16.
// ---------------------------------------------------------------------------
#define HSR    40
#define HABUF  (128 * HSR)
#define STGB   (2 * HABUF * 2)          // 20480 bytes
#define NSTG   3
#define PIPE_SMEM (NSTG * STGB)         // 61440 bytes

__device__ __forceinline__ void gemm_mainloop(
    const __half* __restrict__ X, const __half* __restrict__ Wt,
    int m0, int n0, __half* sm, float c[2][8][4])
{
    const int tid  = threadIdx.x;
    const int lane = tid & 31;
    const int wid  = tid >> 5;
    const int warpM = wid & 3;
    const int warpN = wid >> 2;
    const int lrow = lane & 15;
    const int lcol = (lane >> 4) * 8;

    const uint32_t smbase = smem_u32(sm);
    const int arow = tid >> 1;
    const int ab   = (tid & 1) * 32;
    const __half* srcA0 = X  + (size_t)(m0 + arow) * DIM + (tid & 1) * 16;
    const __half* srcB0 = Wt + (size_t)(n0 + arow) * DIM + (tid & 1) * 16;
    const uint32_t dstA0 = smbase + arow * (HSR * 2) + ab;

    const uint32_t aoff0 = ((warpM * 32 +      lrow) * HSR + lcol) * 2;
    const uint32_t aoff1 = ((warpM * 32 + 16 + lrow) * HSR + lcol) * 2;
    uint32_t boff[4];
#pragma unroll
    for (int ng = 0; ng < 4; ng++)
        boff[ng] = 2 * HABUF + ((warpN * 64 + ng * 16 + lrow) * HSR + lcol) * 2;

#define ISSUE(stage, ch) do {                                   \
        uint32_t dA = dstA0 + (stage) * STGB;                   \
        const __half* sA = srcA0 + (ch) * 32;                   \
        cp16(dA, sA); cp16(dA + 16, sA + 8);                    \
        uint32_t dB = dA + HABUF * 2;                           \
        const __half* sB = srcB0 + (ch) * 32;                   \
        cp16(dB, sB); cp16(dB + 16, sB + 8);                    \
    } while (0)

    ISSUE(0, 0); CP_COMMIT();
    ISSUE(1, 1); CP_COMMIT();

    const int NCHK = DIM / 32;   // 16
    for (int ch = 0; ch < NCHK; ch++) {
        CP_WAIT1();
        __syncthreads();
        if (ch + 2 < NCHK) ISSUE((ch + 2) % NSTG, ch + 2);
        CP_COMMIT();

        const uint32_t stg = smbase + (ch % NSTG) * STGB;
#pragma unroll
        for (int ks = 0; ks < 2; ks++) {
            const uint32_t kso = ks * 32;
            uint32_t af[2][4];
            ldsm_x4(af[0], stg + aoff0 + kso);
            ldsm_x4(af[1], stg + aoff1 + kso);
#pragma unroll
            for (int ng = 0; ng < 4; ng++) {
                uint32_t bq[4];
                ldsm_x4(bq, stg + boff[ng] + kso);
#pragma unroll
                for (int mt = 0; mt < 2; mt++) {
                    mma_f16(c[mt][ng * 2],     af[mt], bq[0], bq[2]);
                    mma_f16(c[mt][ng * 2 + 1], af[mt], bq[1], bq[3]);
                }
            }
        }
    }
#undef ISSUE
}

// ---------------------------------------------------------------------------
// Fused a/b/g projections (z picks weight/bias/output/act), fp16 out
// ---------------------------------------------------------------------------
__global__ __launch_bounds__(256) void gemm3_h(
    const __half* __restrict__ X, const __half* __restrict__ Wth,
    const float* __restrict__ ba, const float* __restrict__ bbi,
    const float* __restrict__ bg,
    __half* __restrict__ Ca, __half* __restrict__ Cb, __half* __restrict__ Cg)
{
    extern __shared__ __half sm[];
    const int z = blockIdx.z;
    const __half* Wt = Wth + (size_t)z * DIM * DIM;
    const float* bias = (z == 0) ? ba : (z == 1) ? bbi : bg;
    __half* C = (z == 0) ? Ca : (z == 1) ? Cb : Cg;
    const int act = (z == 1) ? 0 : 1;
    const int m0 = blockIdx.y * 128;
    const int n0 = blockIdx.x * 128;

    float c[2][8][4];
#pragma unroll
    for (int mt = 0; mt < 2; mt++)
#pragma unroll
        for (int nt = 0; nt < 8; nt++)
#pragma unroll
            for (int r = 0; r < 4; r++) c[mt][nt][r] = 0.0f;

    gemm_mainloop(X, Wt, m0, n0, sm, c);

    const int lane = threadIdx.x & 31;
    const int wid  = threadIdx.x >> 5;
    const int g    = lane >> 2;
    const int t4   = lane & 3;
    const int warpM = wid & 3;
    const int warpN = wid >> 2;
#pragma unroll
    for (int mt = 0; mt < 2; mt++) {
#pragma unroll
        for (int nt = 0; nt < 8; nt++) {
            const int row  = m0 + warpM * 32 + mt * 16 + g;
            const int coln = n0 + warpN * 64 + nt * 8 + t4 * 2;
            const float b0 = bias[coln], b1 = bias[coln + 1];
            float v0 = c[mt][nt][0] + b0;
            float v1 = c[mt][nt][1] + b1;
            float v2 = c[mt][nt][2] + b0;
            float v3 = c[mt][nt][3] + b1;
            if (act) {
                v0 = 1.0f / (1.0f + __expf(-v0));
                v1 = 1.0f / (1.0f + __expf(-v1));
                v2 = 1.0f / (1.0f + __expf(-v2));
                v3 = 1.0f / (1.0f + __expf(-v3));
            }
            *(__half2*)&C[(size_t)row * DIM + coln]       = __floats2half2_rn(v0, v1);
            *(__half2*)&C[(size_t)(row + 8) * DIM + coln] = __floats2half2_rn(v2, v3);
        }
    }
}

// ---------------------------------------------------------------------------
// Final projection + merge: out = hg @ Wo^T + bo + g_rout
// ---------------------------------------------------------------------------
__global__ __launch_bounds__(256) void gemm1_f(
    const __half* __restrict__ X, const __half* __restrict__ Wt,
    const float* __restrict__ bias, const float* __restrict__ R,
    float* __restrict__ C)
{
    extern __shared__ __half sm[];
    const int m0 = blockIdx.y * 128;
    const int n0 = blockIdx.x * 128;

    float c[2][8][4];
#pragma unroll
    for (int mt = 0; mt < 2; mt++)
#pragma unroll
        for (int nt = 0; nt < 8; nt++)
#pragma unroll
            for (int r = 0; r < 4; r++) c[mt][nt][r] = 0.0f;

    gemm_mainloop(X, Wt, m0, n0, sm, c);

    const int lane = threadIdx.x & 31;
    const int wid  = threadIdx.x >> 5;
    const int g    = lane >> 2;
    const int t4   = lane & 3;
    const int warpM = wid & 3;
    const int warpN = wid >> 2;
#pragma unroll
    for (int mt = 0; mt < 2; mt++) {
#pragma unroll
        for (int nt = 0; nt < 8; nt++) {
            const int row  = m0 + warpM * 32 + mt * 16 + g;
            const int coln = n0 + warpN * 64 + nt * 8 + t4 * 2;
            const float b0 = bias[coln], b1 = bias[coln + 1];
            float2 r0 = *(const float2*)&R[(size_t)row * DIM + coln];
            float2 r1 = *(const float2*)&R[(size_t)(row + 8) * DIM + coln];
            *(float2*)&C[(size_t)row * DIM + coln] =
                make_float2(c[mt][nt][0] + b0 + r0.x, c[mt][nt][1] + b1 + r0.y);
            *(float2*)&C[(size_t)(row + 8) * DIM + coln] =
                make_float2(c[mt][nt][2] + b0 + r1.x, c[mt][nt][3] + b1 + r1.y);
        }
    }
}

// ---------------------------------------------------------------------------
// Chunked linear scan (CHUNK=16 -> 512 blocks per phase)
// ---------------------------------------------------------------------------
__global__ __launch_bounds__(256) void scan_chunks_h()
{
    const int d2 = threadIdx.x;
    const int c  = blockIdx.x;
    const int bb = blockIdx.y;
    const __half2* pa = (const __half2*)g_ah;
    const __half2* pb = (const __half2*)g_bh;
    size_t base = ((size_t)(bb * TT + c * CHUNK) * DIM) / 2 + d2;
    float A0 = 1.0f, A1 = 1.0f, h0 = 0.0f, h1 = 0.0f;
#pragma unroll
    for (int t = 0; t < CHUNK; t++) {
        float2 af = __half22float2(pa[base + (size_t)t * 256]);
        float2 bf = __half22float2(pb[base + (size_t)t * 256]);
        h0 = fmaf(af.x, h0, bf.x);
        h1 = fmaf(af.y, h1, bf.y);
        A0 *= af.x; A1 *= af.y;
    }
    const int idx = (bb * NCH + c) * DIM + 2 * d2;
    g_cA[idx] = A0; g_cA[idx + 1] = A1;
    g_cB[idx] = h0; g_cB[idx + 1] = h1;
}

__global__ __launch_bounds__(512) void scan_carry()
{
    const int d  = threadIdx.x;
    const int bb = blockIdx.x;
    float h = 0.0f;
#pragma unroll 8
    for (int c = 0; c < NCH; c++) {
        const int idx = (bb * NCH + c) * DIM + d;
        g_pref[idx] = h;
        h = fmaf(g_cA[idx], h, g_cB[idx]);
    }
}

__global__ __launch_bounds__(256) void scan_apply_h()
{
    const int d2 = threadIdx.x;
    const int c  = blockIdx.x;
    const int bb = blockIdx.y;
    const __half2* pa = (const __half2*)g_ah;
    const __half2* pb = (const __half2*)g_bh;
    const __half2* pg = (const __half2*)g_gh;
    __half2* phg = (__half2*)g_hgh;
    size_t base = ((size_t)(bb * TT + c * CHUNK) * DIM) / 2 + d2;
    float2 pf = *(float2*)&g_pref[(bb * NCH + c) * DIM + 2 * d2];
    float h0 = pf.x, h1 = pf.y;
#pragma unroll
    for (int t = 0; t < CHUNK; t++) {
        float2 af = __half22float2(pa[base + (size_t)t * 256]);
        float2 bf = __half22float2(pb[base + (size_t)t * 256]);
        float2 gf = __half22float2(pg[base + (size_t)t * 256]);
        h0 = fmaf(af.x, h0, bf.x);
        h1 = fmaf(af.y, h1, bf.y);
        phg[base + (size_t)t * 256] = __floats2half2_rn(h0 * gf.x, h1 * gf.y);
    }
}

// ---------------------------------------------------------------------------
// Retention: fp16 inputs, cp.async double-buffered K/V tiles, ldmatrix
// fragments (V via ldmatrix.trans — no transpose staging). WIN=256.
// smem rows padded to 72 halves (144 B): conflict-free ldsm, 16B aligned.
// ---------------------------------------------------------------------------
#define RST     72                       // halves per tile row
#define RTILE   (64 * RST)               // halves per tile (4608)
#define ROFF_Q  0
#define ROFF_K0 (RTILE)
#define ROFF_K1 (2 * RTILE)
#define ROFF_V0 (3 * RTILE)
#define ROFF_V1 (4 * RTILE)
#define ROFF_S  (5 * RTILE)
#define RET_SMEM (6 * RTILE * 2)         // 55296 bytes

__device__ __forceinline__ uint32_t packh2(float lo, float hi) {
    __half2 h = __floats2half2_rn(lo, hi);
    return *(uint32_t*)&h;
}

__global__ __launch_bounds__(256) void retention_mma(
    const __half* __restrict__ qh, const __half* __restrict__ kh,
    const __half* __restrict__ vh, float* __restrict__ out)
{
    extern __shared__ __half rsm[];
    const int tid  = threadIdx.x;
    const int lane = tid & 31;
    const int wid  = tid >> 5;
    const int g    = lane >> 2;
    const int t4   = lane & 3;
    const int tb   = (wid & 3) * 16;      // warp t-strip
    const int nb   = (wid >> 2) * 32;     // warp n-strip
    const int lrow  = lane & 15;
    const int lcolb = (lane >> 4) * 16;

    const int t0 = blockIdx.x * TBLK;
    const int hh = blockIdx.y;
    const int bb = blockIdx.z;

    const __half* qb = qh + (size_t)bb * TT * DIM + hh * DH;
    const __half* kb = kh + (size_t)bb * TT * DIM + hh * DH;
    const __half* vb = vh + (size_t)bb * TT * DIM + hh * DH;

    const uint32_t smb   = smem_u32(rsm);
    const uint32_t qbase = smb;
    const uint32_t kbase[2] = { smb + ROFF_K0 * 2, smb + ROFF_K1 * 2 };
    const uint32_t vbase[2] = { smb + ROFF_V0 * 2, smb + ROFF_V1 * 2 };
    const uint32_t sbase = smb + ROFF_S * 2;

    // copy mapping: 4 threads per row, 2x16B segments each (row = 128B data)
    const int crow = tid >> 2;            // 0..63
    const int cs16 = (tid & 3) * 32;      // byte offset of first segment
    const uint32_t cdst = crow * 144 + cs16;
    const int csrc = (tid & 3) * 16;      // halves offset

    const int sBeg = (t0 >= WIN) ? (t0 - WIN) : 0;
    const int nchk = (t0 - sBeg) / SCH + 1;

#define RISSUE(buf, s0) do {                                                  \
        const __half* ks = kb + (size_t)((s0) + crow) * DIM + csrc;           \
        const __half* vs = vb + (size_t)((s0) + crow) * DIM + csrc;           \
        cp16(kbase[buf] + cdst,      ks);                                     \
        cp16(kbase[buf] + cdst + 16, ks + 8);                                 \
        cp16(vbase[buf] + cdst,      vs);                                     \
        cp16(vbase[buf] + cdst + 16, vs + 8);                                 \
    } while (0)

    // group 0: Q tile + chunk 0
    {
        const __half* qs = qb + (size_t)(t0 + crow) * DIM + csrc;
        cp16(qbase + cdst,      qs);
        cp16(qbase + cdst + 16, qs + 8);
        RISSUE(0, sBeg);
    }
    CP_COMMIT();
    if (nchk > 1) RISSUE(1, sBeg + SCH);
    CP_COMMIT();

    // per-thread D^{-s} factors
    float dsv[4][2];
    dsv[0][0] = exp2f(-L2DECAY * (float)(nb + 2 * t4));
    dsv[0][1] = dsv[0][0] * DINV;
#pragma unroll
    for (int nf = 1; nf < 4; nf++) {
        dsv[nf][0] = dsv[nf-1][0] * DM8INV;
        dsv[nf][1] = dsv[nf-1][1] * DM8INV;
    }

    float co[4][4];
#pragma unroll
    for (int nf = 0; nf < 4; nf++)
#pragma unroll
        for (int r = 0; r < 4; r++) co[nf][r] = 0.0f;

    uint32_t afq[4][4];

    for (int ci = 0; ci < nchk; ci++) {
        const int buf = ci & 1;
        if (ci + 1 < nchk) CP_WAIT1(); else CP_WAIT0();
        __syncthreads();

        if (ci == 0) {
#pragma unroll
            for (int kk = 0; kk < 4; kk++)
                ldsm_x4(afq[kk], qbase + (tb + lrow) * 144 + kk * 32 + lcolb);
        }

        // ---- S = Q . K^T ----
        float cs[4][4];
#pragma unroll
        for (int nf = 0; nf < 4; nf++)
#pragma unroll
            for (int r = 0; r < 4; r++) cs[nf][r] = 0.0f;
#pragma unroll
        for (int kk = 0; kk < 4; kk++) {
#pragma unroll
            for (int ng = 0; ng < 2; ng++) {
                uint32_t bq[4];
                ldsm_x4(bq, kbase[buf] + (nb + ng * 16 + lrow) * 144 + kk * 32 + lcolb);
                mma_f16(cs[ng * 2],     afq[kk], bq[0], bq[2]);
                mma_f16(cs[ng * 2 + 1], afq[kk], bq[1], bq[3]);
            }
        }

        // ---- decay + causal mask, store S as fp16 ----
        const int s0  = sBeg + ci * SCH;
        const int off = t0 - s0;
        const float Dt0 = exp2f((float)(tb + g + off) * L2DECAY);
        const float Dt1 = Dt0 * D8;
        uint32_t* Su = (uint32_t*)(rsm + ROFF_S);
#pragma unroll
        for (int nf = 0; nf < 4; nf++) {
            const int scol = nb + nf * 8 + 2 * t4;
            const int d0 = tb + g + off - scol;
            float w00 = (d0     >= 0) ? Dt0 * dsv[nf][0] : 0.0f;
            float w01 = (d0 - 1 >= 0) ? Dt0 * dsv[nf][1] : 0.0f;
            float w10 = (d0 + 8 >= 0) ? Dt1 * dsv[nf][0] : 0.0f;
            float w11 = (d0 + 7 >= 0) ? Dt1 * dsv[nf][1] : 0.0f;
            Su[(tb + g)     * 36 + (nb >> 1) + nf * 4 + t4] = packh2(cs[nf][0] * w00, cs[nf][1] * w01);
            Su[(tb + g + 8) * 36 + (nb >> 1) + nf * 4 + t4] = packh2(cs[nf][2] * w10, cs[nf][3] * w11);
        }
        __syncthreads();

        // ---- O += S . V  (V fragments via ldmatrix.trans on row-major V) ----
#pragma unroll
        for (int kk = 0; kk < 4; kk++) {
            uint32_t as[4];
            ldsm_x4(as, sbase + (tb + lrow) * 144 + kk * 32 + lcolb);
#pragma unroll
            for (int ng = 0; ng < 2; ng++) {
                uint32_t bq[4];
                ldsm_x4_t(bq, vbase[buf] + (kk * 16 + lrow) * 144
                              + (nb + ng * 16) * 2 + lcolb);
                mma_f16(co[ng * 2],     as, bq[0], bq[1]);
                mma_f16(co[ng * 2 + 1], as, bq[2], bq[3]);
            }
        }
        __syncthreads();   // all warps done reading K/V buf before refill

        if (ci + 2 < nchk) RISSUE(buf, sBeg + (ci + 2) * SCH);
        CP_COMMIT();
    }
#undef RISSUE

    // pure store into g_rout (merged later by gemm1_f)
#pragma unroll
    for (int nf = 0; nf < 4; nf++) {
        const int col = hh * DH + nb + nf * 8 + 2 * t4;
        *(float2*)&out[((size_t)bb * TT + t0 + tb + g)     * DIM + col] =
            make_float2(co[nf][0], co[nf][1]);
        *(float2*)&out[((size_t)bb * TT + t0 + tb + g + 8) * DIM + col] =
            make_float2(co[nf][2], co[nf][3]);
    }
}

// ---------------------------------------------------------------------------
extern "C" void kernel_launch(void* const* d_in, const int* in_sizes, int n_in,
                              void* d_out, int out_size)
{
    const float* q  = (const float*)d_in[0];
    const float* k  = (const float*)d_in[1];
    const float* v  = (const float*)d_in[2];
    const float* Wa = (const float*)d_in[3];
    const float* ba = (const float*)d_in[4];
    const float* Wb = (const float*)d_in[5];
    const float* bb = (const float*)d_in[6];
    const float* Wg = (const float*)d_in[7];
    const float* bg = (const float*)d_in[8];
    const float* Wo = (const float*)d_in[9];
    const float* bo = (const float*)d_in[10];
    float* out = (float*)d_out;

    __half *pah, *pbh, *pgh, *phgh, *pqh, *pkh, *pvh, *pwth;
    float *prout;
    cudaGetSymbolAddress((void**)&pah,  g_ah);
    cudaGetSymbolAddress((void**)&pbh,  g_bh);
    cudaGetSymbolAddress((void**)&pgh,  g_gh);
    cudaGetSymbolAddress((void**)&phgh, g_hgh);
    cudaGetSymbolAddress((void**)&pqh,  g_qh);
    cudaGetSymbolAddress((void**)&pkh,  g_kh);
    cudaGetSymbolAddress((void**)&pvh,  g_vh);
    cudaGetSymbolAddress((void**)&pwth, g_Wth);
    cudaGetSymbolAddress((void**)&prout, g_rout);

    cudaFuncSetAttribute(gemm3_h, cudaFuncAttributeMaxDynamicSharedMemorySize, PIPE_SMEM);
    cudaFuncSetAttribute(gemm1_f, cudaFuncAttributeMaxDynamicSharedMemorySize, PIPE_SMEM);
    cudaFuncSetAttribute(retention_mma, cudaFuncAttributeMaxDynamicSharedMemorySize, RET_SMEM);

    cudaStream_t s2;
    cudaStreamCreateWithFlags(&s2, cudaStreamNonBlocking);
    cudaEvent_t eFork, eW, eG3, eJoin;
    cudaEventCreateWithFlags(&eFork, cudaEventDisableTiming);
    cudaEventCreateWithFlags(&eW,    cudaEventDisableTiming);
    cudaEventCreateWithFlags(&eG3,   cudaEventDisableTiming);
    cudaEventCreateWithFlags(&eJoin, cudaEventDisableTiming);

    const int f2hGrid = (MROWS * DIM) / (256 * 8);

    // Side stream: W transpose + k/v fp16 converts (overlap main's f2h/gemm3).
    cudaEventRecord(eFork, 0);
    cudaStreamWaitEvent(s2, eFork, 0);
    transposeW4h<<<dim3(DIM / 32, DIM / 32, 4), dim3(32, 8), 0, s2>>>(
        Wa, Wb, Wg, Wo, pwth);
    cudaEventRecord(eW, s2);
    f2h_bulk<<<f2hGrid, 256, 0, s2>>>(k, pkh);
    f2h_bulk<<<f2hGrid, 256, 0, s2>>>(v, pvh);

    // Main: q -> fp16, then the three projections (needs eW).
    f2h_bulk<<<f2hGrid, 256>>>(q, pqh);
    cudaStreamWaitEvent(0, eW, 0);
    gemm3_h<<<dim3(DIM / 128, MROWS / 128, 3), 256, PIPE_SMEM>>>(
        pqh, pwth, ba, bb, bg, pah, pbh, pgh);
    cudaEventRecord(eG3, 0);

    // Side stream: retention after gemm3 (overlaps DRAM-bound scans).
    cudaStreamWaitEvent(s2, eG3, 0);
    retention_mma<<<dim3(TT / TBLK, NH, BB), 256, RET_SMEM, s2>>>(
        pqh, pkh, pvh, prout);
    cudaEventRecord(eJoin, s2);

    // Main: scans (DRAM-bound, co-run with retention).
    scan_chunks_h<<<dim3(NCH, BB), 256>>>();
    scan_carry<<<BB, 512>>>();
    scan_apply_h<<<dim3(NCH, BB), 256>>>();

    // Join retention, then merging final projection.
    cudaStreamWaitEvent(0, eJoin, 0);
    gemm1_f<<<dim3(DIM / 128, MROWS / 128, 1), 256, PIPE_SMEM>>>(
        phgh, pwth + 3 * DIM * DIM, bo, prout, out);
}